// round 2
// baseline (speedup 1.0000x reference)
#include <cuda_runtime.h>

#define B_ 256
#define T_ 1024
#define K_ 128

__device__ float g_logz[B_];
__device__ float g_gold[B_];

__device__ __forceinline__ void fma2(unsigned long long &acc, unsigned long long a, unsigned long long b) {
    asm("fma.rn.f32x2 %0, %1, %2, %0;" : "+l"(acc) : "l"(a), "l"(b));
}
__device__ __forceinline__ unsigned long long add2(unsigned long long a, unsigned long long b) {
    unsigned long long c;
    asm("add.rn.f32x2 %0, %1, %2;" : "=l"(c) : "l"(a), "l"(b));
    return c;
}
__device__ __forceinline__ unsigned long long pack2(float x, float y) {
    unsigned long long r;
    asm("mov.b64 %0, {%1, %2};" : "=l"(r) : "f"(x), "f"(y));
    return r;
}
__device__ __forceinline__ float2 unpack2(unsigned long long v) {
    float2 f;
    asm("mov.b64 {%0, %1}, %2;" : "=f"(f.x), "=f"(f.y) : "l"(v));
    return f;
}
__device__ __forceinline__ float warp_max(float v) {
    #pragma unroll
    for (int o = 16; o > 0; o >>= 1) v = fmaxf(v, __shfl_xor_sync(0xffffffffu, v, o));
    return v;
}
__device__ __forceinline__ float warp_sum(float v) {
    #pragma unroll
    for (int o = 16; o > 0; o >>= 1) v += __shfl_xor_sync(0xffffffffu, v, o);
    return v;
}

// Forward logZ: one batch per CTA of 128 threads. Thread j owns output state j.
// E column j (exp(trans[:,j])) lives in registers as 64 packed f32x2 pairs.
// p = exp(alpha) lives in smem (double-buffered), read broadcast.
__global__ __launch_bounds__(128, 2) void crf_fwd(
    const float* __restrict__ emis,   // (B,T,K)
    const int* __restrict__ mask,     // (B,T) int32 (bool upcast)
    const float* __restrict__ start,  // (K)
    const float* __restrict__ endv,   // (K)
    const float* __restrict__ trans)  // (K,K)
{
    const int b = blockIdx.x;
    const int j = threadIdx.x;
    __shared__ __align__(16) float pbuf[2][K_];
    __shared__ float wred[4];

    // E[:,j] as packed pairs over i (column of exp(trans))
    unsigned long long e2[K_ / 2];
    #pragma unroll
    for (int k = 0; k < K_ / 2; ++k) {
        float ea = __expf(trans[(2 * k) * K_ + j]);
        float eb = __expf(trans[(2 * k + 1) * K_ + j]);
        e2[k] = pack2(ea, eb);
    }

    const float* __restrict__ eb = emis + (size_t)b * T_ * K_;
    const int* __restrict__ mb = mask + (size_t)b * T_;

    float alpha = start[j] + eb[j];   // t = 0
    float C = 0.0f;                   // accumulated log-shift

    // prefetch emissions/mask 2 steps ahead to hide DRAM latency
    float em_a = eb[1 * K_ + j];
    float em_b = eb[2 * K_ + j];
    int mk_a = mb[1];
    int mk_b = mb[2];

    for (int t = 1; t < T_; ++t) {
        float em = em_a; em_a = em_b;
        int mk = mk_a; mk_a = mk_b;
        if (t + 2 < T_) { em_b = eb[(size_t)(t + 2) * K_ + j]; mk_b = mb[t + 2]; }

        // p_j = exp(alpha_j)  (alpha renormalized every 4 steps -> arg <= ~36)
        pbuf[t & 1][j] = __expf(alpha);
        __syncthreads();

        // GEMV: s_j = sum_i p_i * E[i][j], packed f32x2 over i-pairs
        const ulonglong2* __restrict__ pv = (const ulonglong2*)pbuf[t & 1];
        unsigned long long a0 = 0ull, a1 = 0ull, a2 = 0ull, a3 = 0ull;
        #pragma unroll
        for (int k = 0; k < 32; k += 2) {
            ulonglong2 q0 = pv[k];
            ulonglong2 q1 = pv[k + 1];
            fma2(a0, q0.x, e2[2 * k]);
            fma2(a1, q0.y, e2[2 * k + 1]);
            fma2(a2, q1.x, e2[2 * k + 2]);
            fma2(a3, q1.y, e2[2 * k + 3]);
        }
        a0 = add2(a0, a1);
        a2 = add2(a2, a3);
        a0 = add2(a0, a2);
        float2 sp = unpack2(a0);
        float s = sp.x + sp.y;

        float anew = __logf(s) + em;
        alpha = mk ? anew : alpha;

        // periodic renormalization: subtract CTA max, accumulate into C
        if ((t & 3) == 0) {
            float m = warp_max(alpha);
            if ((j & 31) == 0) wred[j >> 5] = m;
            __syncthreads();
            m = fmaxf(fmaxf(wred[0], wred[1]), fmaxf(wred[2], wred[3]));
            alpha -= m;
            C += m;
        }
    }

    // logZ_b = C + logsumexp_j(alpha_j + end_j)
    float v = alpha + endv[j];
    float m = warp_max(v);
    if ((j & 31) == 0) wred[j >> 5] = m;
    __syncthreads();
    m = fmaxf(fmaxf(wred[0], wred[1]), fmaxf(wred[2], wred[3]));
    float e = __expf(v - m);
    float ws = warp_sum(e);
    __syncthreads();
    if ((j & 31) == 0) wred[j >> 5] = ws;
    __syncthreads();
    if (j == 0) {
        float s = (wred[0] + wred[1]) + (wred[2] + wred[3]);
        g_logz[b] = C + m + __logf(s);
    }
}

// Gold path score: one batch per CTA of 128 threads, strided over t.
__global__ void crf_gold(
    const float* __restrict__ emis,
    const int* __restrict__ tags,   // (B,T) int32 (int64 downcast by harness)
    const int* __restrict__ mask,   // (B,T) int32
    const float* __restrict__ start,
    const float* __restrict__ endv,
    const float* __restrict__ trans)
{
    const int b = blockIdx.x;
    const int tid = threadIdx.x;
    const float* __restrict__ eb = emis + (size_t)b * T_ * K_;
    const int* __restrict__ tg = tags + (size_t)b * T_;
    const int* __restrict__ mb = mask + (size_t)b * T_;

    float sc = 0.0f;
    int cnt = 0;
    for (int t = tid; t < T_; t += 128) {
        int mt = mb[t];
        cnt += mt ? 1 : 0;
        if (t >= 1 && mt && mb[t - 1]) {
            int pr = tg[t - 1]; pr = pr < 0 ? 0 : pr;
            int cr = tg[t];     cr = cr < 0 ? 0 : cr;
            sc += trans[pr * K_ + cr] + eb[(size_t)t * K_ + cr];
        }
    }

    __shared__ float wsc[4];
    __shared__ int wcn[4];
    float s = warp_sum(sc);
    int c = cnt;
    #pragma unroll
    for (int o = 16; o > 0; o >>= 1) c += __shfl_xor_sync(0xffffffffu, c, o);
    if ((tid & 31) == 0) { wsc[tid >> 5] = s; wcn[tid >> 5] = c; }
    __syncthreads();
    if (tid == 0) {
        float total = (wsc[0] + wsc[1]) + (wsc[2] + wsc[3]);
        int ctot = wcn[0] + wcn[1] + wcn[2] + wcn[3];
        int t0 = tg[0];
        float sc0 = (start[t0] + eb[t0]) * (mb[0] ? 1.0f : 0.0f);
        int lenm1 = ctot - 1;
        int last = tg[lenm1];
        g_gold[b] = total + sc0 + endv[last];
    }
}

// Final: mean over batches of (logZ - gold), fixed-order tree reduction.
__global__ void crf_finish(float* __restrict__ out) {
    __shared__ float sm[B_];
    int i = threadIdx.x;
    sm[i] = g_logz[i] - g_gold[i];
    __syncthreads();
    #pragma unroll
    for (int s = 128; s > 0; s >>= 1) {
        if (i < s) sm[i] += sm[i + s];
        __syncthreads();
    }
    if (i == 0) out[0] = sm[0] * (1.0f / B_);
}

extern "C" void kernel_launch(void* const* d_in, const int* in_sizes, int n_in,
                              void* d_out, int out_size) {
    const float* emis   = (const float*)d_in[0];
    const int* tags     = (const int*)d_in[1];
    const int* mask     = (const int*)d_in[2];
    const float* start  = (const float*)d_in[3];
    const float* endv   = (const float*)d_in[4];
    const float* trans  = (const float*)d_in[5];
    float* out = (float*)d_out;

    crf_fwd<<<B_, K_>>>(emis, mask, start, endv, trans);
    crf_gold<<<B_, K_>>>(emis, tags, mask, start, endv, trans);
    crf_finish<<<1, B_>>>(out);
}